// round 14
// baseline (speedup 1.0000x reference)
#include <cuda_runtime.h>
#include <cuda_fp16.h>
#include <cstdint>

// Problem constants
#define Bb 2
#define Sq 2048
#define Ee 1024
#define Hh 16
#define Dd 64
#define Mrows (Bb*Sq)   // 4096

// Scratch (device globals: allocation-free, graph-capturable)
__device__ __half g_xh[(size_t)Mrows*Ee];                  // x fp16
__device__ __half g_wah[(size_t)3*Ee*Ee];                  // W_attn fp16
__device__ __half g_wph[(size_t)Ee*Ee];                    // W_proj fp16
__device__ __half g_qh[(size_t)Bb*Hh*Sq*Dd];               // q fp16 (pre-scaled by 0.125*log2e)
__device__ __half g_kh[(size_t)Bb*Hh*Sq*Dd];               // k fp16
__device__ __half g_vth[(size_t)Bb*Hh*Dd*Sq];              // V^T fp16 [bh][d][s]
__device__ __half g_oh[(size_t)Mrows*Ee];                  // attn out fp16

// ---------------------------------------------------------------------------
// helpers (all plain sm_80-era PTX: valid on compute_103 virtual arch)
// ---------------------------------------------------------------------------
__device__ __forceinline__ uint32_t smem_u32(const void* p) {
    uint32_t a;
    asm("{ .reg .u64 t; cvta.to.shared.u64 t, %1; cvt.u32.u64 %0, t; }"
        : "=r"(a) : "l"(p));
    return a;
}
#define CPA(dst, src) \
    asm volatile("cp.async.cg.shared.global [%0], [%1], 16;" :: "r"(dst), "l"(src))
#define CP_COMMIT() asm volatile("cp.async.commit_group;")
#define CP_WAIT1()  asm volatile("cp.async.wait_group 1;" ::: "memory")
#define CP_WAIT0()  asm volatile("cp.async.wait_group 0;" ::: "memory")

#define LDSM4(r, addr) \
    asm volatile("ldmatrix.sync.aligned.m8n8.x4.shared.b16 {%0,%1,%2,%3}, [%4];" \
        : "=r"((r)[0]), "=r"((r)[1]), "=r"((r)[2]), "=r"((r)[3]) : "r"(addr))

__device__ __forceinline__ void mma_f16(float* c, const uint32_t* a,
                                        uint32_t b0, uint32_t b1) {
    asm volatile(
        "mma.sync.aligned.m16n8k16.row.col.f32.f16.f16.f32 "
        "{%0,%1,%2,%3}, {%4,%5,%6,%7}, {%8,%9}, {%0,%1,%2,%3};"
        : "+f"(c[0]), "+f"(c[1]), "+f"(c[2]), "+f"(c[3])
        : "r"(a[0]), "r"(a[1]), "r"(a[2]), "r"(a[3]), "r"(b0), "r"(b1));
}

__device__ __forceinline__ uint32_t pack2(__half lo, __half hi) {
    __half2 t(lo, hi);
    return *(uint32_t*)&t;
}

// single-instruction base-2 exponential (MUFU.EX2)
__device__ __forceinline__ float ex2(float x) {
    float y;
    asm("ex2.approx.f32 %0, %1;" : "=f"(y) : "f"(x));
    return y;
}

// ---------------------------------------------------------------------------
// fused fp32 -> fp16 conversion for x, W_attn, W_proj (one launch, 8/thread)
// ---------------------------------------------------------------------------
#define NX (Mrows*Ee)          // 4194304
#define NWA (3*Ee*Ee)          // 3145728
#define NWP (Ee*Ee)            // 1048576

__global__ __launch_bounds__(256)
void conv_all(const float* __restrict__ x, const float* __restrict__ wa,
              const float* __restrict__ wp, __half* __restrict__ xh,
              __half* __restrict__ wah, __half* __restrict__ wph)
{
    int i = (blockIdx.x * 256 + threadIdx.x) * 8;
    const float* src; __half* dst; int off;
    if (i < NX)            { src = x;  dst = xh;  off = 0; }
    else if (i < NX + NWA) { src = wa; dst = wah; off = NX; }
    else                   { src = wp; dst = wph; off = NX + NWA; }
    int j = i - off;
    float4 v0 = *(const float4*)(src + j);
    float4 v1 = *(const float4*)(src + j + 4);
    uint32_t r[4];
    r[0] = pack2(__float2half(v0.x), __float2half(v0.y));
    r[1] = pack2(__float2half(v0.z), __float2half(v0.w));
    r[2] = pack2(__float2half(v1.x), __float2half(v1.y));
    r[3] = pack2(__float2half(v1.z), __float2half(v1.w));
    *(uint4*)(dst + j) = make_uint4(r[0], r[1], r[2], r[3]);
}

// ---------------------------------------------------------------------------
// GEMM: C[M,N] = A_f16[M,K] @ B_f16[N,K]^T + bias  (single fp16 product)
// 128x128 CTA tile, 8 warps (warp tile 32x64), K-chunk 64, cp.async 2-stage,
// ldmatrix.x4, 2 CTAs/SM. smem stage: A,B each [128][72] half -> 36864B.
// (2-stage is the proven optimum; 3-stage regressed in round 13.)
// ---------------------------------------------------------------------------
#define GST   36864
#define GSMEM (2*GST)

template<int SCATTER>
__global__ __launch_bounds__(256, 2)
void gemm_mma(const __half* __restrict__ Ag, const __half* __restrict__ Bg,
              const float* __restrict__ bias, float* __restrict__ C,
              __half* __restrict__ Qh, __half* __restrict__ Kh,
              __half* __restrict__ Vth,
              int M, int N, int K)
{
    extern __shared__ __align__(16) char smg[];
    uint32_t sb = smem_u32(smg);
    int tid = threadIdx.x;
    int lane = tid & 31, warp = tid >> 5;
    int wm = warp >> 1, wn = warp & 1;
    int g = lane >> 2, t2 = (lane & 3) * 2;
    int m0 = blockIdx.y * 128, n0 = blockIdx.x * 128;

    uint32_t aOff = (uint32_t)((wm * 32 + (lane & 15)) * 144 + ((lane >> 4) << 3) * 2);
    uint32_t bOff = (uint32_t)((wn * 64 + ((lane >> 4) << 3) + (lane & 7)) * 144 +
                               (((lane >> 3) & 1) << 3) * 2);

    const __half* srcs[2] = { Ag + (size_t)m0 * K, Bg + (size_t)n0 * K };

    auto load_chunk = [&](int kt, int st) {
        uint32_t stb = sb + st * GST;
        #pragma unroll
        for (int b = 0; b < 2; b++) {
            const __half* base = srcs[b] + kt;
            #pragma unroll
            for (int it = 0; it < 4; it++) {
                int idx = tid + it * 256;            // 0..1023
                int r = idx >> 3, cg = idx & 7;      // 128 rows x 8 chunks(16B)
                CPA(stb + b * 18432 + r * 144 + cg * 16,
                    base + (size_t)r * K + cg * 8);
            }
        }
        CP_COMMIT();
    };

    float acc[2][8][4] = {};
    load_chunk(0, 0);
    int nch = K >> 6;
    for (int c = 0; c < nch; c++) {
        if (c + 1 < nch) { load_chunk((c + 1) * 64, (c + 1) & 1); CP_WAIT1(); }
        else             { CP_WAIT0(); }
        __syncthreads();
        uint32_t stb = sb + (c & 1) * GST;
        #pragma unroll
        for (int kk = 0; kk < 64; kk += 16) {
            uint32_t aF[2][4];
            LDSM4(aF[0], stb + aOff + kk * 2);
            LDSM4(aF[1], stb + aOff + kk * 2 + 16 * 144);
            #pragma unroll
            for (int j2 = 0; j2 < 4; j2++) {
                uint32_t bf[4];
                LDSM4(bf, stb + 18432 + bOff + j2 * 2304 + kk * 2);
                mma_f16(acc[0][2*j2],   aF[0], bf[0], bf[1]);
                mma_f16(acc[1][2*j2],   aF[1], bf[0], bf[1]);
                mma_f16(acc[0][2*j2+1], aF[0], bf[2], bf[3]);
                mma_f16(acc[1][2*j2+1], aF[1], bf[2], bf[3]);
            }
        }
        __syncthreads();
    }

    // epilogue
    const float QSC = 0.125f * 1.44269504088896f;   // fold scale*log2(e) into q
    #pragma unroll
    for (int i = 0; i < 2; i++) {
        #pragma unroll
        for (int e2 = 0; e2 < 2; e2++) {
            int m = m0 + wm * 32 + i * 16 + g + e2 * 8;
            #pragma unroll
            for (int j = 0; j < 8; j++) {
                int n = n0 + wn * 64 + j * 8 + t2;
                float v0 = acc[i][j][e2*2+0] + bias[n];
                float v1 = acc[i][j][e2*2+1] + bias[n+1];
                if (SCATTER == 0) {
                    *(float2*)(C + (size_t)m * N + n) = make_float2(v0, v1);
                } else {
                    int part = n >> 10, e = n & 1023, hh = e >> 6, d = e & 63;
                    int b = m >> 11, s = m & 2047;
                    int bh = b * Hh + hh;
                    if (part == 0) {
                        size_t i0 = ((size_t)bh * Sq + s) * Dd + d;
                        *(__half2*)(Qh + i0) =
                            __half2(__float2half(v0 * QSC), __float2half(v1 * QSC));
                    } else if (part == 1) {
                        size_t i0 = ((size_t)bh * Sq + s) * Dd + d;
                        *(__half2*)(Kh + i0) =
                            __half2(__float2half(v0), __float2half(v1));
                    } else {
                        size_t i0 = ((size_t)bh * Dd + d) * Sq + s;
                        Vth[i0]      = __float2half(v0);
                        Vth[i0 + Sq] = __float2half(v1);
                    }
                }
            }
        }
    }
}

// ---------------------------------------------------------------------------
// Output-projection GEMM with 64x64 tiles (fine granularity for SM balance):
// 1024 CTAs of 4.2 MMAC each -> max 7 tiles/SM = 29.4 MMAC vs 33.6 for the
// 128x128 tiling. 128 threads, 4 warps (warp tile 32x32), K-chunk 64,
// cp.async 2-stage. Accumulation order per output element is identical to
// the 128-tile kernel (same K-chunk/kk/mma order) -> bitwise-same numerics.
// smem stage: A,B each [64][72] half = 9216B -> 18432B/stage.
// ---------------------------------------------------------------------------
#define G0ST   18432
#define G0SMEM (2*G0ST)

__global__ __launch_bounds__(128, 4)
void gemm0_64(const __half* __restrict__ Ag, const __half* __restrict__ Bg,
              const float* __restrict__ bias, float* __restrict__ C,
              int M, int N, int K)
{
    extern __shared__ __align__(16) char smg[];
    uint32_t sb = smem_u32(smg);
    int tid = threadIdx.x;
    int lane = tid & 31, warp = tid >> 5;
    int wm = warp >> 1, wn = warp & 1;
    int g = lane >> 2, t2 = (lane & 3) * 2;
    int m0 = blockIdx.y * 64, n0 = blockIdx.x * 64;

    uint32_t aOff = (uint32_t)((wm * 32 + (lane & 15)) * 144 + ((lane >> 4) << 3) * 2);
    uint32_t bOff = (uint32_t)((wn * 32 + ((lane >> 4) << 3) + (lane & 7)) * 144 +
                               (((lane >> 3) & 1) << 3) * 2);

    const __half* srcs[2] = { Ag + (size_t)m0 * K, Bg + (size_t)n0 * K };

    auto load_chunk = [&](int kt, int st) {
        uint32_t stb = sb + st * G0ST;
        #pragma unroll
        for (int b = 0; b < 2; b++) {
            const __half* base = srcs[b] + kt;
            #pragma unroll
            for (int it = 0; it < 4; it++) {
                int idx = tid + it * 128;            // 0..511
                int r = idx >> 3, cg = idx & 7;      // 64 rows x 8 chunks(16B)
                CPA(stb + b * 9216 + r * 144 + cg * 16,
                    base + (size_t)r * K + cg * 8);
            }
        }
        CP_COMMIT();
    };

    float acc[2][4][4] = {};
    load_chunk(0, 0);
    int nch = K >> 6;
    for (int c = 0; c < nch; c++) {
        if (c + 1 < nch) { load_chunk((c + 1) * 64, (c + 1) & 1); CP_WAIT1(); }
        else             { CP_WAIT0(); }
        __syncthreads();
        uint32_t stb = sb + (c & 1) * G0ST;
        #pragma unroll
        for (int kk = 0; kk < 64; kk += 16) {
            uint32_t aF[2][4];
            LDSM4(aF[0], stb + aOff + kk * 2);
            LDSM4(aF[1], stb + aOff + kk * 2 + 16 * 144);
            #pragma unroll
            for (int j2 = 0; j2 < 2; j2++) {
                uint32_t bf[4];
                LDSM4(bf, stb + 9216 + bOff + j2 * 2304 + kk * 2);
                mma_f16(acc[0][2*j2],   aF[0], bf[0], bf[1]);
                mma_f16(acc[1][2*j2],   aF[1], bf[0], bf[1]);
                mma_f16(acc[0][2*j2+1], aF[0], bf[2], bf[3]);
                mma_f16(acc[1][2*j2+1], aF[1], bf[2], bf[3]);
            }
        }
        __syncthreads();
    }

    // epilogue: fp32 + bias
    #pragma unroll
    for (int i = 0; i < 2; i++) {
        #pragma unroll
        for (int e2 = 0; e2 < 2; e2++) {
            int m = m0 + wm * 32 + i * 16 + g + e2 * 8;
            #pragma unroll
            for (int j = 0; j < 4; j++) {
                int n = n0 + wn * 32 + j * 8 + t2;
                float v0 = acc[i][j][e2*2+0] + bias[n];
                float v1 = acc[i][j][e2*2+1] + bias[n+1];
                *(float2*)(C + (size_t)m * N + n) = make_float2(v0, v1);
            }
        }
    }
}

// ---------------------------------------------------------------------------
// Flash attention, single fp16, 128-key smem tiles (two 64-key compute passes)
// CTA: 128 q rows, 8 warps (16 q rows each). cp.async 2-stage, ex2 softmax.
// Grid is (bh, tile) with tile-major = GLOBAL heavy-first launch order (LPT).
// smem: Q [128][72]; per stage K [128][72] + Vt [64][136].
// ---------------------------------------------------------------------------
#define AQ    18432
#define AKST  18432
#define AVST  17408
#define ASTG  (AKST + AVST)        // 35840
#define ASMEM (AQ + 2*ASTG)        // 90112

__global__ __launch_bounds__(256, 2)
void attn_mma(const __half* __restrict__ Qg, const __half* __restrict__ Khg,
              const __half* __restrict__ Vhg, __half* __restrict__ Oh)
{
    extern __shared__ __align__(16) char sma[];
    uint32_t sb = smem_u32(sma);
    int tid = threadIdx.x, lane = tid & 31, w = tid >> 5;
    int g = lane >> 2, t2 = (lane & 3) * 2;
    int bh = blockIdx.x;                        // fast dim = bh
    int qt = gridDim.y - 1 - (int)blockIdx.y;   // slow dim = tile, heavy first
    int q0 = qt * 128;
    int hflip = w & 1;                          // phase stagger (neutral, kept)

    uint32_t qOff = (uint32_t)((w * 16 + (lane & 15)) * 144 + ((lane >> 4) << 3) * 2);
    uint32_t kOff = (uint32_t)((((lane >> 4) << 3) + (lane & 7)) * 144 +
                               (((lane >> 3) & 1) << 3) * 2);
    uint32_t vOff = (uint32_t)((((lane >> 4) << 3) + (lane & 7)) * 272 +
                               (((lane >> 3) & 1) << 3) * 2);

    const __half* Khb = Khg + (size_t)bh * Sq * Dd;
    const __half* Vhb = Vhg + (size_t)bh * Dd * Sq;

    // Q tile -> smem
    {
        const __half* qp = Qg + ((size_t)bh * Sq + q0) * Dd;
        #pragma unroll
        for (int it = 0; it < 4; it++) {
            int idx = tid + it * 256;           // 0..1023
            int r = idx >> 3, cg = idx & 7;     // 128 rows x 8 chunks
            CPA(sb + r * 144 + cg * 16, qp + (size_t)r * Dd + cg * 8);
        }
        CP_COMMIT();
    }

    auto load_tile = [&](int t, int st) {
        uint32_t stb = sb + AQ + st * ASTG;
        int k0 = t * 128;
        // K: 128 key rows x 64 d
        #pragma unroll
        for (int it = 0; it < 4; it++) {
            int idx = tid + it * 256;
            int r = idx >> 3, cg = idx & 7;
            CPA(stb + r * 144 + cg * 16, Khb + (size_t)(k0 + r) * Dd + cg * 8);
        }
        // Vt: 64 d rows x 128 keys
        #pragma unroll
        for (int it = 0; it < 4; it++) {
            int idx = tid + it * 256;           // 0..1023
            int r = idx >> 4, cg = idx & 15;    // 64 rows x 16 chunks(16B)
            CPA(stb + AKST + r * 272 + cg * 16, Vhb + (size_t)r * Sq + k0 + cg * 8);
        }
        CP_COMMIT();
    };

    int T = qt + 1;
    load_tile(0, 0);

    float o[8][4] = {};
    float m0r = -1e30f, m1r = -1e30f, l0 = 0.f, l1 = 0.f;
    int qwmin = q0 + w * 16;

    for (int t = 0; t < T; t++) {
        if (t + 1 < T) { load_tile(t + 1, (t + 1) & 1); CP_WAIT1(); }
        else           { CP_WAIT0(); }
        __syncthreads();
        uint32_t kb = sb + AQ + (t & 1) * ASTG;

        #pragma unroll
        for (int hp = 0; hp < 2; hp++) {
            int h = hp ^ hflip;                   // odd warps: reverse half order
            int kbase = 128 * t + 64 * h;
            if (kbase <= qwmin + 15) {
                uint32_t kh = kb + h * 9216;          // 64 key rows into K buffer
                uint32_t vh = kb + AKST + h * 128;    // 64 key cols into Vt buffer

                // ---- QK ----
                float s[8][4] = {};
                #pragma unroll
                for (int ks = 0; ks < 4; ks++) {
                    int kk = ks * 16;
                    uint32_t aF[4];
                    LDSM4(aF, sb + qOff + kk * 2);
                    #pragma unroll
                    for (int jp = 0; jp < 2; jp++) {
                        int j2a = 2 * jp, j2b = 2 * jp + 1;
                        uint32_t b0[4], b1[4];
                        LDSM4(b0, kh + kOff + j2a * 2304 + kk * 2);
                        LDSM4(b1, kh + kOff + j2b * 2304 + kk * 2);
                        mma_f16(s[2*j2a],   aF, b0[0], b0[1]);
                        mma_f16(s[2*j2a+1], aF, b0[2], b0[3]);
                        mma_f16(s[2*j2b],   aF, b1[0], b1[1]);
                        mma_f16(s[2*j2b+1], aF, b1[2], b1[3]);
                    }
                }

                // ---- causal mask ----
                if (kbase + 63 > qwmin) {
                    int qr0 = qwmin + g, qr1 = qwmin + g + 8;
                    #pragma unroll
                    for (int j = 0; j < 8; j++) {
                        int kbi = kbase + j * 8 + t2;
                        if (kbi     > qr0) s[j][0] = -1e30f;
                        if (kbi + 1 > qr0) s[j][1] = -1e30f;
                        if (kbi     > qr1) s[j][2] = -1e30f;
                        if (kbi + 1 > qr1) s[j][3] = -1e30f;
                    }
                }

                // ---- online softmax (base-2; q pre-scaled by log2e; MUFU ex2) ----
                float mx0 = -1e30f, mx1 = -1e30f;
                #pragma unroll
                for (int j = 0; j < 8; j++) {
                    mx0 = fmaxf(mx0, fmaxf(s[j][0], s[j][1]));
                    mx1 = fmaxf(mx1, fmaxf(s[j][2], s[j][3]));
                }
                #pragma unroll
                for (int off = 1; off < 4; off <<= 1) {
                    mx0 = fmaxf(mx0, __shfl_xor_sync(0xffffffffu, mx0, off, 4));
                    mx1 = fmaxf(mx1, __shfl_xor_sync(0xffffffffu, mx1, off, 4));
                }
                mx0 = fmaxf(mx0, m0r);
                mx1 = fmaxf(mx1, m1r);
                float al0 = ex2(m0r - mx0), al1 = ex2(m1r - mx1);
                m0r = mx0; m1r = mx1;
                l0 *= al0;  l1 *= al1;
                #pragma unroll
                for (int j = 0; j < 8; j++) {
                    s[j][0] = ex2(s[j][0] - mx0);
                    s[j][1] = ex2(s[j][1] - mx0);
                    s[j][2] = ex2(s[j][2] - mx1);
                    s[j][3] = ex2(s[j][3] - mx1);
                    l0 += s[j][0] + s[j][1];
                    l1 += s[j][2] + s[j][3];
                    o[j][0] *= al0; o[j][1] *= al0;
                    o[j][2] *= al1; o[j][3] *= al1;
                }

                // ---- PV (P single fp16) ----
                #pragma unroll
                for (int ks = 0; ks < 4; ks++) {
                    int j0 = 2 * ks, j1 = 2 * ks + 1;
                    uint32_t pF[4];
                    pF[0] = pack2(__float2half(s[j0][0]), __float2half(s[j0][1]));
                    pF[1] = pack2(__float2half(s[j0][2]), __float2half(s[j0][3]));
                    pF[2] = pack2(__float2half(s[j1][0]), __float2half(s[j1][1]));
                    pF[3] = pack2(__float2half(s[j1][2]), __float2half(s[j1][3]));
                    #pragma unroll
                    for (int jp = 0; jp < 2; jp++) {
                        int j2a = 2 * jp, j2b = 2 * jp + 1;
                        uint32_t v0[4], v1[4];
                        LDSM4(v0, vh + vOff + j2a * 4352 + ks * 32);
                        LDSM4(v1, vh + vOff + j2b * 4352 + ks * 32);
                        mma_f16(o[2*j2a],   pF, v0[0], v0[1]);
                        mma_f16(o[2*j2a+1], pF, v0[2], v0[3]);
                        mma_f16(o[2*j2b],   pF, v1[0], v1[1]);
                        mma_f16(o[2*j2b+1], pF, v1[2], v1[3]);
                    }
                }
            }
        }
        __syncthreads();
    }

    // ---- finalize ----
    #pragma unroll
    for (int off = 1; off < 4; off <<= 1) {
        l0 += __shfl_xor_sync(0xffffffffu, l0, off, 4);
        l1 += __shfl_xor_sync(0xffffffffu, l1, off, 4);
    }
    float inv0 = 1.f / l0, inv1 = 1.f / l1;
    int b = bh >> 4, hh = bh & 15;
    int r0 = q0 + w * 16 + g, r1 = r0 + 8;
    #pragma unroll
    for (int j = 0; j < 8; j++) {
        int d = j * 8 + t2;
        size_t i0 = ((size_t)(b * Sq + r0)) * Ee + hh * Dd + d;
        *(__half2*)(Oh + i0) =
            __half2(__float2half(o[j][0] * inv0), __float2half(o[j][1] * inv0));
        size_t i1 = ((size_t)(b * Sq + r1)) * Ee + hh * Dd + d;
        *(__half2*)(Oh + i1) =
            __half2(__float2half(o[j][2] * inv1), __float2half(o[j][3] * inv1));
    }
}

// ---------------------------------------------------------------------------
extern "C" void kernel_launch(void* const* d_in, const int* in_sizes, int n_in,
                              void* d_out, int out_size)
{
    const float* x      = (const float*)d_in[0];
    const float* W_attn = (const float*)d_in[1];
    const float* b_attn = (const float*)d_in[2];
    const float* W_proj = (const float*)d_in[3];
    const float* b_proj = (const float*)d_in[4];
    float* out = (float*)d_out;

    __half *xh, *wah, *wph, *qh, *kh, *vth, *oh;
    cudaGetSymbolAddress((void**)&xh, g_xh);
    cudaGetSymbolAddress((void**)&wah, g_wah);
    cudaGetSymbolAddress((void**)&wph, g_wph);
    cudaGetSymbolAddress((void**)&qh, g_qh);
    cudaGetSymbolAddress((void**)&kh, g_kh);
    cudaGetSymbolAddress((void**)&vth, g_vth);
    cudaGetSymbolAddress((void**)&oh, g_oh);

    cudaFuncSetAttribute(gemm_mma<1>, cudaFuncAttributeMaxDynamicSharedMemorySize, GSMEM);
    cudaFuncSetAttribute(gemm0_64,    cudaFuncAttributeMaxDynamicSharedMemorySize, G0SMEM);
    cudaFuncSetAttribute(attn_mma,    cudaFuncAttributeMaxDynamicSharedMemorySize, ASMEM);

    // 0) fp32 -> fp16 conversions (single fused launch, 8 elems/thread)
    conv_all<<<(NX + NWA + NWP) / 2048, 256>>>(x, W_attn, W_proj, xh, wah, wph);

    // 1) QKV projection -> q (scaled by 0.125*log2e), k, V^T   (all fp16)
    gemm_mma<1><<<dim3(3*Ee/128, Mrows/128), 256, GSMEM>>>(
        xh, wah, b_attn, nullptr, qh, kh, vth, Mrows, 3*Ee, Ee);

    // 2) Causal flash attention -> merged-head fp16
    //    Grid (bh, tile): tile-major order => global heavy-first (LPT) schedule
    attn_mma<<<dim3(Bb*Hh, Sq/128), 256, ASMEM>>>(qh, kh, vth, oh);

    // 3) Output projection -> fp32 out (64x64 tiles for SM load balance)
    gemm0_64<<<dim3(Ee/64, Mrows/64), 128, G0SMEM>>>(
        oh, wph, b_proj, out, Mrows, Ee, Ee);
}

// round 15
// speedup vs baseline: 1.0237x; 1.0237x over previous
#include <cuda_runtime.h>
#include <cuda_fp16.h>
#include <cstdint>

// Problem constants
#define Bb 2
#define Sq 2048
#define Ee 1024
#define Hh 16
#define Dd 64
#define Mrows (Bb*Sq)   // 4096

// Scratch (device globals: allocation-free, graph-capturable)
__device__ __half g_xh[(size_t)Mrows*Ee];                  // x fp16
__device__ __half g_wah[(size_t)3*Ee*Ee];                  // W_attn fp16
__device__ __half g_wph[(size_t)Ee*Ee];                    // W_proj fp16
__device__ __half g_qh[(size_t)Bb*Hh*Sq*Dd];               // q fp16 (pre-scaled by 0.125*log2e)
__device__ __half g_kh[(size_t)Bb*Hh*Sq*Dd];               // k fp16
__device__ __half g_vth[(size_t)Bb*Hh*Dd*Sq];              // V^T fp16 [bh][d][s]
__device__ __half g_oh[(size_t)Mrows*Ee];                  // attn out fp16

// ---------------------------------------------------------------------------
// helpers (all plain sm_80-era PTX: valid on compute_103 virtual arch)
// ---------------------------------------------------------------------------
__device__ __forceinline__ uint32_t smem_u32(const void* p) {
    uint32_t a;
    asm("{ .reg .u64 t; cvta.to.shared.u64 t, %1; cvt.u32.u64 %0, t; }"
        : "=r"(a) : "l"(p));
    return a;
}
#define CPA(dst, src) \
    asm volatile("cp.async.cg.shared.global [%0], [%1], 16;" :: "r"(dst), "l"(src))
#define CP_COMMIT() asm volatile("cp.async.commit_group;")
#define CP_WAIT1()  asm volatile("cp.async.wait_group 1;" ::: "memory")
#define CP_WAIT0()  asm volatile("cp.async.wait_group 0;" ::: "memory")

#define LDSM4(r, addr) \
    asm volatile("ldmatrix.sync.aligned.m8n8.x4.shared.b16 {%0,%1,%2,%3}, [%4];" \
        : "=r"((r)[0]), "=r"((r)[1]), "=r"((r)[2]), "=r"((r)[3]) : "r"(addr))

__device__ __forceinline__ void mma_f16(float* c, const uint32_t* a,
                                        uint32_t b0, uint32_t b1) {
    asm volatile(
        "mma.sync.aligned.m16n8k16.row.col.f32.f16.f16.f32 "
        "{%0,%1,%2,%3}, {%4,%5,%6,%7}, {%8,%9}, {%0,%1,%2,%3};"
        : "+f"(c[0]), "+f"(c[1]), "+f"(c[2]), "+f"(c[3])
        : "r"(a[0]), "r"(a[1]), "r"(a[2]), "r"(a[3]), "r"(b0), "r"(b1));
}

__device__ __forceinline__ uint32_t pack2(__half lo, __half hi) {
    __half2 t(lo, hi);
    return *(uint32_t*)&t;
}

// single-instruction base-2 exponential (MUFU.EX2)
__device__ __forceinline__ float ex2(float x) {
    float y;
    asm("ex2.approx.f32 %0, %1;" : "=f"(y) : "f"(x));
    return y;
}

// ---------------------------------------------------------------------------
// fused fp32 -> fp16 conversion for x, W_attn, W_proj (one launch, 8/thread)
// ---------------------------------------------------------------------------
#define NX (Mrows*Ee)          // 4194304
#define NWA (3*Ee*Ee)          // 3145728
#define NWP (Ee*Ee)            // 1048576

__global__ __launch_bounds__(256)
void conv_all(const float* __restrict__ x, const float* __restrict__ wa,
              const float* __restrict__ wp, __half* __restrict__ xh,
              __half* __restrict__ wah, __half* __restrict__ wph)
{
    int i = (blockIdx.x * 256 + threadIdx.x) * 8;
    const float* src; __half* dst; int off;
    if (i < NX)            { src = x;  dst = xh;  off = 0; }
    else if (i < NX + NWA) { src = wa; dst = wah; off = NX; }
    else                   { src = wp; dst = wph; off = NX + NWA; }
    int j = i - off;
    float4 v0 = *(const float4*)(src + j);
    float4 v1 = *(const float4*)(src + j + 4);
    uint32_t r[4];
    r[0] = pack2(__float2half(v0.x), __float2half(v0.y));
    r[1] = pack2(__float2half(v0.z), __float2half(v0.w));
    r[2] = pack2(__float2half(v1.x), __float2half(v1.y));
    r[3] = pack2(__float2half(v1.z), __float2half(v1.w));
    *(uint4*)(dst + j) = make_uint4(r[0], r[1], r[2], r[3]);
}

// ---------------------------------------------------------------------------
// GEMM: C[M,N] = A_f16[M,K] @ B_f16[N,K]^T + bias  (single fp16 product)
// 128x128 CTA tile, 8 warps (warp tile 32x64), K-chunk 64, cp.async 2-stage,
// ldmatrix.x4, 2 CTAs/SM. smem stage: A,B each [128][72] half -> 36864B.
// (Round-12 proven configuration.)
// ---------------------------------------------------------------------------
#define GST   36864
#define GSMEM (2*GST)

template<int SCATTER>
__global__ __launch_bounds__(256, 2)
void gemm_mma(const __half* __restrict__ Ag, const __half* __restrict__ Bg,
              const float* __restrict__ bias, float* __restrict__ C,
              __half* __restrict__ Qh, __half* __restrict__ Kh,
              __half* __restrict__ Vth,
              int M, int N, int K)
{
    extern __shared__ __align__(16) char smg[];
    uint32_t sb = smem_u32(smg);
    int tid = threadIdx.x;
    int lane = tid & 31, warp = tid >> 5;
    int wm = warp >> 1, wn = warp & 1;
    int g = lane >> 2, t2 = (lane & 3) * 2;
    int m0 = blockIdx.y * 128, n0 = blockIdx.x * 128;

    uint32_t aOff = (uint32_t)((wm * 32 + (lane & 15)) * 144 + ((lane >> 4) << 3) * 2);
    uint32_t bOff = (uint32_t)((wn * 64 + ((lane >> 4) << 3) + (lane & 7)) * 144 +
                               (((lane >> 3) & 1) << 3) * 2);

    const __half* srcs[2] = { Ag + (size_t)m0 * K, Bg + (size_t)n0 * K };

    auto load_chunk = [&](int kt, int st) {
        uint32_t stb = sb + st * GST;
        #pragma unroll
        for (int b = 0; b < 2; b++) {
            const __half* base = srcs[b] + kt;
            #pragma unroll
            for (int it = 0; it < 4; it++) {
                int idx = tid + it * 256;            // 0..1023
                int r = idx >> 3, cg = idx & 7;      // 128 rows x 8 chunks(16B)
                CPA(stb + b * 18432 + r * 144 + cg * 16,
                    base + (size_t)r * K + cg * 8);
            }
        }
        CP_COMMIT();
    };

    float acc[2][8][4] = {};
    load_chunk(0, 0);
    int nch = K >> 6;
    for (int c = 0; c < nch; c++) {
        if (c + 1 < nch) { load_chunk((c + 1) * 64, (c + 1) & 1); CP_WAIT1(); }
        else             { CP_WAIT0(); }
        __syncthreads();
        uint32_t stb = sb + (c & 1) * GST;
        #pragma unroll
        for (int kk = 0; kk < 64; kk += 16) {
            uint32_t aF[2][4];
            LDSM4(aF[0], stb + aOff + kk * 2);
            LDSM4(aF[1], stb + aOff + kk * 2 + 16 * 144);
            #pragma unroll
            for (int j2 = 0; j2 < 4; j2++) {
                uint32_t bf[4];
                LDSM4(bf, stb + 18432 + bOff + j2 * 2304 + kk * 2);
                mma_f16(acc[0][2*j2],   aF[0], bf[0], bf[1]);
                mma_f16(acc[1][2*j2],   aF[1], bf[0], bf[1]);
                mma_f16(acc[0][2*j2+1], aF[0], bf[2], bf[3]);
                mma_f16(acc[1][2*j2+1], aF[1], bf[2], bf[3]);
            }
        }
        __syncthreads();
    }

    // epilogue
    const float QSC = 0.125f * 1.44269504088896f;   // fold scale*log2(e) into q
    #pragma unroll
    for (int i = 0; i < 2; i++) {
        #pragma unroll
        for (int e2 = 0; e2 < 2; e2++) {
            int m = m0 + wm * 32 + i * 16 + g + e2 * 8;
            #pragma unroll
            for (int j = 0; j < 8; j++) {
                int n = n0 + wn * 64 + j * 8 + t2;
                float v0 = acc[i][j][e2*2+0] + bias[n];
                float v1 = acc[i][j][e2*2+1] + bias[n+1];
                if (SCATTER == 0) {
                    *(float2*)(C + (size_t)m * N + n) = make_float2(v0, v1);
                } else {
                    int part = n >> 10, e = n & 1023, hh = e >> 6, d = e & 63;
                    int b = m >> 11, s = m & 2047;
                    int bh = b * Hh + hh;
                    if (part == 0) {
                        size_t i0 = ((size_t)bh * Sq + s) * Dd + d;
                        *(__half2*)(Qh + i0) =
                            __half2(__float2half(v0 * QSC), __float2half(v1 * QSC));
                    } else if (part == 1) {
                        size_t i0 = ((size_t)bh * Sq + s) * Dd + d;
                        *(__half2*)(Kh + i0) =
                            __half2(__float2half(v0), __float2half(v1));
                    } else {
                        size_t i0 = ((size_t)bh * Dd + d) * Sq + s;
                        Vth[i0]      = __float2half(v0);
                        Vth[i0 + Sq] = __float2half(v1);
                    }
                }
            }
        }
    }
}

// ---------------------------------------------------------------------------
// Flash attention, single fp16, 128-key smem tiles (two 64-key compute passes)
// CTA: 128 q rows, 8 warps (16 q rows each). cp.async 2-stage, ex2 softmax.
// Grid is (bh, tile) with tile-major = GLOBAL heavy-first launch order (LPT).
// Diagonal passes skip provably-all-masked 16-key blocks in QK and PV
// (exact: skipped QK blocks are masked to -1e30 anyway; skipped PV blocks
// have P == 0 exactly via ex2 underflow).
// smem: Q [128][72]; per stage K [128][72] + Vt [64][136].
// ---------------------------------------------------------------------------
#define AQ    18432
#define AKST  18432
#define AVST  17408
#define ASTG  (AKST + AVST)        // 35840
#define ASMEM (AQ + 2*ASTG)        // 90112

__global__ __launch_bounds__(256, 2)
void attn_mma(const __half* __restrict__ Qg, const __half* __restrict__ Khg,
              const __half* __restrict__ Vhg, __half* __restrict__ Oh)
{
    extern __shared__ __align__(16) char sma[];
    uint32_t sb = smem_u32(sma);
    int tid = threadIdx.x, lane = tid & 31, w = tid >> 5;
    int g = lane >> 2, t2 = (lane & 3) * 2;
    int bh = blockIdx.x;                        // fast dim = bh
    int qt = gridDim.y - 1 - (int)blockIdx.y;   // slow dim = tile, heavy first
    int q0 = qt * 128;
    int hflip = w & 1;                          // phase stagger (neutral, kept)

    uint32_t qOff = (uint32_t)((w * 16 + (lane & 15)) * 144 + ((lane >> 4) << 3) * 2);
    uint32_t kOff = (uint32_t)((((lane >> 4) << 3) + (lane & 7)) * 144 +
                               (((lane >> 3) & 1) << 3) * 2);
    uint32_t vOff = (uint32_t)((((lane >> 4) << 3) + (lane & 7)) * 272 +
                               (((lane >> 3) & 1) << 3) * 2);

    const __half* Khb = Khg + (size_t)bh * Sq * Dd;
    const __half* Vhb = Vhg + (size_t)bh * Dd * Sq;

    // Q tile -> smem
    {
        const __half* qp = Qg + ((size_t)bh * Sq + q0) * Dd;
        #pragma unroll
        for (int it = 0; it < 4; it++) {
            int idx = tid + it * 256;           // 0..1023
            int r = idx >> 3, cg = idx & 7;     // 128 rows x 8 chunks
            CPA(sb + r * 144 + cg * 16, qp + (size_t)r * Dd + cg * 8);
        }
        CP_COMMIT();
    }

    auto load_tile = [&](int t, int st) {
        uint32_t stb = sb + AQ + st * ASTG;
        int k0 = t * 128;
        // K: 128 key rows x 64 d
        #pragma unroll
        for (int it = 0; it < 4; it++) {
            int idx = tid + it * 256;
            int r = idx >> 3, cg = idx & 7;
            CPA(stb + r * 144 + cg * 16, Khb + (size_t)(k0 + r) * Dd + cg * 8);
        }
        // Vt: 64 d rows x 128 keys
        #pragma unroll
        for (int it = 0; it < 4; it++) {
            int idx = tid + it * 256;           // 0..1023
            int r = idx >> 4, cg = idx & 15;    // 64 rows x 16 chunks(16B)
            CPA(stb + AKST + r * 272 + cg * 16, Vhb + (size_t)r * Sq + k0 + cg * 8);
        }
        CP_COMMIT();
    };

    int T = qt + 1;
    load_tile(0, 0);

    float o[8][4] = {};
    float m0r = -1e30f, m1r = -1e30f, l0 = 0.f, l1 = 0.f;
    int qwmin = q0 + w * 16;

    for (int t = 0; t < T; t++) {
        if (t + 1 < T) { load_tile(t + 1, (t + 1) & 1); CP_WAIT1(); }
        else           { CP_WAIT0(); }
        __syncthreads();
        uint32_t kb = sb + AQ + (t & 1) * ASTG;

        #pragma unroll
        for (int hp = 0; hp < 2; hp++) {
            int h = hp ^ hflip;                   // odd warps: reverse half order
            int kbase = 128 * t + 64 * h;
            if (kbase <= qwmin + 15) {
                uint32_t kh = kb + h * 9216;          // 64 key rows into K buffer
                uint32_t vh = kb + AKST + h * 128;    // 64 key cols into Vt buffer
                int kmax = qwmin + 15;                // last unmasked key for this warp

                // ---- QK (skip fully-masked 16-key blocks) ----
                float s[8][4] = {};
                #pragma unroll
                for (int ks = 0; ks < 4; ks++) {
                    int kk = ks * 16;
                    uint32_t aF[4];
                    LDSM4(aF, sb + qOff + kk * 2);
                    #pragma unroll
                    for (int j2 = 0; j2 < 4; j2++) {
                        if (kbase + j2 * 16 <= kmax) {
                            uint32_t bf[4];
                            LDSM4(bf, kh + kOff + j2 * 2304 + kk * 2);
                            mma_f16(s[2*j2],   aF, bf[0], bf[1]);
                            mma_f16(s[2*j2+1], aF, bf[2], bf[3]);
                        }
                    }
                }

                // ---- causal mask ----
                if (kbase + 63 > qwmin) {
                    int qr0 = qwmin + g, qr1 = qwmin + g + 8;
                    #pragma unroll
                    for (int j = 0; j < 8; j++) {
                        int kbi = kbase + j * 8 + t2;
                        if (kbi     > qr0) s[j][0] = -1e30f;
                        if (kbi + 1 > qr0) s[j][1] = -1e30f;
                        if (kbi     > qr1) s[j][2] = -1e30f;
                        if (kbi + 1 > qr1) s[j][3] = -1e30f;
                    }
                }

                // ---- online softmax (base-2; q pre-scaled by log2e; MUFU ex2) ----
                float mx0 = -1e30f, mx1 = -1e30f;
                #pragma unroll
                for (int j = 0; j < 8; j++) {
                    mx0 = fmaxf(mx0, fmaxf(s[j][0], s[j][1]));
                    mx1 = fmaxf(mx1, fmaxf(s[j][2], s[j][3]));
                }
                #pragma unroll
                for (int off = 1; off < 4; off <<= 1) {
                    mx0 = fmaxf(mx0, __shfl_xor_sync(0xffffffffu, mx0, off, 4));
                    mx1 = fmaxf(mx1, __shfl_xor_sync(0xffffffffu, mx1, off, 4));
                }
                mx0 = fmaxf(mx0, m0r);
                mx1 = fmaxf(mx1, m1r);
                float al0 = ex2(m0r - mx0), al1 = ex2(m1r - mx1);
                m0r = mx0; m1r = mx1;
                l0 *= al0;  l1 *= al1;
                #pragma unroll
                for (int j = 0; j < 8; j++) {
                    s[j][0] = ex2(s[j][0] - mx0);
                    s[j][1] = ex2(s[j][1] - mx0);
                    s[j][2] = ex2(s[j][2] - mx1);
                    s[j][3] = ex2(s[j][3] - mx1);
                    l0 += s[j][0] + s[j][1];
                    l1 += s[j][2] + s[j][3];
                    o[j][0] *= al0; o[j][1] *= al0;
                    o[j][2] *= al1; o[j][3] *= al1;
                }

                // ---- PV (P single fp16; skip 16-key blocks with P == 0) ----
                #pragma unroll
                for (int ks = 0; ks < 4; ks++) {
                    if (kbase + ks * 16 <= kmax) {
                        int j0 = 2 * ks, j1 = 2 * ks + 1;
                        uint32_t pF[4];
                        pF[0] = pack2(__float2half(s[j0][0]), __float2half(s[j0][1]));
                        pF[1] = pack2(__float2half(s[j0][2]), __float2half(s[j0][3]));
                        pF[2] = pack2(__float2half(s[j1][0]), __float2half(s[j1][1]));
                        pF[3] = pack2(__float2half(s[j1][2]), __float2half(s[j1][3]));
                        #pragma unroll
                        for (int j2 = 0; j2 < 4; j2++) {
                            uint32_t vf[4];
                            LDSM4(vf, vh + vOff + j2 * 4352 + ks * 32);
                            mma_f16(o[2*j2],   pF, vf[0], vf[1]);
                            mma_f16(o[2*j2+1], pF, vf[2], vf[3]);
                        }
                    }
                }
            }
        }
        __syncthreads();
    }

    // ---- finalize ----
    #pragma unroll
    for (int off = 1; off < 4; off <<= 1) {
        l0 += __shfl_xor_sync(0xffffffffu, l0, off, 4);
        l1 += __shfl_xor_sync(0xffffffffu, l1, off, 4);
    }
    float inv0 = 1.f / l0, inv1 = 1.f / l1;
    int b = bh >> 4, hh = bh & 15;
    int r0 = q0 + w * 16 + g, r1 = r0 + 8;
    #pragma unroll
    for (int j = 0; j < 8; j++) {
        int d = j * 8 + t2;
        size_t i0 = ((size_t)(b * Sq + r0)) * Ee + hh * Dd + d;
        *(__half2*)(Oh + i0) =
            __half2(__float2half(o[j][0] * inv0), __float2half(o[j][1] * inv0));
        size_t i1 = ((size_t)(b * Sq + r1)) * Ee + hh * Dd + d;
        *(__half2*)(Oh + i1) =
            __half2(__float2half(o[j][2] * inv1), __float2half(o[j][3] * inv1));
    }
}

// ---------------------------------------------------------------------------
extern "C" void kernel_launch(void* const* d_in, const int* in_sizes, int n_in,
                              void* d_out, int out_size)
{
    const float* x      = (const float*)d_in[0];
    const float* W_attn = (const float*)d_in[1];
    const float* b_attn = (const float*)d_in[2];
    const float* W_proj = (const float*)d_in[3];
    const float* b_proj = (const float*)d_in[4];
    float* out = (float*)d_out;

    __half *xh, *wah, *wph, *qh, *kh, *vth, *oh;
    cudaGetSymbolAddress((void**)&xh, g_xh);
    cudaGetSymbolAddress((void**)&wah, g_wah);
    cudaGetSymbolAddress((void**)&wph, g_wph);
    cudaGetSymbolAddress((void**)&qh, g_qh);
    cudaGetSymbolAddress((void**)&kh, g_kh);
    cudaGetSymbolAddress((void**)&vth, g_vth);
    cudaGetSymbolAddress((void**)&oh, g_oh);

    cudaFuncSetAttribute(gemm_mma<0>, cudaFuncAttributeMaxDynamicSharedMemorySize, GSMEM);
    cudaFuncSetAttribute(gemm_mma<1>, cudaFuncAttributeMaxDynamicSharedMemorySize, GSMEM);
    cudaFuncSetAttribute(attn_mma,    cudaFuncAttributeMaxDynamicSharedMemorySize, ASMEM);

    // 0) fp32 -> fp16 conversions (single fused launch, 8 elems/thread)
    conv_all<<<(NX + NWA + NWP) / 2048, 256>>>(x, W_attn, W_proj, xh, wah, wph);

    // 1) QKV projection -> q (scaled by 0.125*log2e), k, V^T   (all fp16)
    gemm_mma<1><<<dim3(3*Ee/128, Mrows/128), 256, GSMEM>>>(
        xh, wah, b_attn, nullptr, qh, kh, vth, Mrows, 3*Ee, Ee);

    // 2) Causal flash attention -> merged-head fp16
    //    Grid (bh, tile): tile-major order => global heavy-first (LPT) schedule
    attn_mma<<<dim3(Bb*Hh, Sq/128), 256, ASMEM>>>(qh, kh, vth, oh);

    // 3) Output projection -> fp32 out (128x128 tiles — round-12 proven config)
    gemm_mma<0><<<dim3(Ee/128, Mrows/128), 256, GSMEM>>>(
        oh, wph, b_proj, out, nullptr, nullptr, nullptr, Mrows, Ee, Ee);
}

// round 16
// speedup vs baseline: 1.0303x; 1.0065x over previous
#include <cuda_runtime.h>
#include <cuda_fp16.h>
#include <cstdint>

// Problem constants
#define Bb 2
#define Sq 2048
#define Ee 1024
#define Hh 16
#define Dd 64
#define Mrows (Bb*Sq)   // 4096

// Scratch (device globals: allocation-free, graph-capturable)
__device__ __half g_xh[(size_t)Mrows*Ee];                  // x fp16
__device__ __half g_wah[(size_t)3*Ee*Ee];                  // W_attn fp16
__device__ __half g_wph[(size_t)Ee*Ee];                    // W_proj fp16
__device__ __half g_qh[(size_t)Bb*Hh*Sq*Dd];               // q fp16 (pre-scaled by 0.125*log2e)
__device__ __half g_kh[(size_t)Bb*Hh*Sq*Dd];               // k fp16
__device__ __half g_vth[(size_t)Bb*Hh*Dd*Sq];              // V^T fp16 [bh][d][s]
__device__ __half g_oh[(size_t)Mrows*Ee];                  // attn out fp16

// ---------------------------------------------------------------------------
// helpers (all plain sm_80-era PTX: valid on compute_103 virtual arch)
// ---------------------------------------------------------------------------
__device__ __forceinline__ uint32_t smem_u32(const void* p) {
    uint32_t a;
    asm("{ .reg .u64 t; cvta.to.shared.u64 t, %1; cvt.u32.u64 %0, t; }"
        : "=r"(a) : "l"(p));
    return a;
}
#define CPA(dst, src) \
    asm volatile("cp.async.cg.shared.global [%0], [%1], 16;" :: "r"(dst), "l"(src))
#define CP_COMMIT() asm volatile("cp.async.commit_group;")
#define CP_WAIT1()  asm volatile("cp.async.wait_group 1;" ::: "memory")
#define CP_WAIT0()  asm volatile("cp.async.wait_group 0;" ::: "memory")

#define LDSM4(r, addr) \
    asm volatile("ldmatrix.sync.aligned.m8n8.x4.shared.b16 {%0,%1,%2,%3}, [%4];" \
        : "=r"((r)[0]), "=r"((r)[1]), "=r"((r)[2]), "=r"((r)[3]) : "r"(addr))

__device__ __forceinline__ void mma_f16(float* c, const uint32_t* a,
                                        uint32_t b0, uint32_t b1) {
    asm volatile(
        "mma.sync.aligned.m16n8k16.row.col.f32.f16.f16.f32 "
        "{%0,%1,%2,%3}, {%4,%5,%6,%7}, {%8,%9}, {%0,%1,%2,%3};"
        : "+f"(c[0]), "+f"(c[1]), "+f"(c[2]), "+f"(c[3])
        : "r"(a[0]), "r"(a[1]), "r"(a[2]), "r"(a[3]), "r"(b0), "r"(b1));
}

__device__ __forceinline__ uint32_t pack2(__half lo, __half hi) {
    __half2 t(lo, hi);
    return *(uint32_t*)&t;
}

// single-instruction base-2 exponential (MUFU.EX2)
__device__ __forceinline__ float ex2(float x) {
    float y;
    asm("ex2.approx.f32 %0, %1;" : "=f"(y) : "f"(x));
    return y;
}

// ---------------------------------------------------------------------------
// fused fp32 -> fp16 conversion for x, W_attn, W_proj (one launch, 8/thread)
// ---------------------------------------------------------------------------
#define NX (Mrows*Ee)          // 4194304
#define NWA (3*Ee*Ee)          // 3145728
#define NWP (Ee*Ee)            // 1048576

__global__ __launch_bounds__(256)
void conv_all(const float* __restrict__ x, const float* __restrict__ wa,
              const float* __restrict__ wp, __half* __restrict__ xh,
              __half* __restrict__ wah, __half* __restrict__ wph)
{
    int i = (blockIdx.x * 256 + threadIdx.x) * 8;
    const float* src; __half* dst; int off;
    if (i < NX)            { src = x;  dst = xh;  off = 0; }
    else if (i < NX + NWA) { src = wa; dst = wah; off = NX; }
    else                   { src = wp; dst = wph; off = NX + NWA; }
    int j = i - off;
    float4 v0 = *(const float4*)(src + j);
    float4 v1 = *(const float4*)(src + j + 4);
    uint32_t r[4];
    r[0] = pack2(__float2half(v0.x), __float2half(v0.y));
    r[1] = pack2(__float2half(v0.z), __float2half(v0.w));
    r[2] = pack2(__float2half(v1.x), __float2half(v1.y));
    r[3] = pack2(__float2half(v1.z), __float2half(v1.w));
    *(uint4*)(dst + j) = make_uint4(r[0], r[1], r[2], r[3]);
}

// ---------------------------------------------------------------------------
// GEMM: C[M,N] = A_f16[M,K] @ B_f16[N,K]^T + bias  (single fp16 product)
// 128x128 CTA tile, 8 warps (warp tile 32x64), K-chunk 64, cp.async 2-stage,
// ldmatrix.x4, 2 CTAs/SM. smem stage: A,B each [128][72] half -> 36864B.
// Part-2 (V^T) output tiles are staged through smem (dead after mainloop)
// and stored with fully-coalesced 16B writes along s. Same values/order.
// ---------------------------------------------------------------------------
#define GST   36864
#define GSMEM (2*GST)

template<int SCATTER>
__global__ __launch_bounds__(256, 2)
void gemm_mma(const __half* __restrict__ Ag, const __half* __restrict__ Bg,
              const float* __restrict__ bias, float* __restrict__ C,
              __half* __restrict__ Qh, __half* __restrict__ Kh,
              __half* __restrict__ Vth,
              int M, int N, int K)
{
    extern __shared__ __align__(16) char smg[];
    uint32_t sb = smem_u32(smg);
    int tid = threadIdx.x;
    int lane = tid & 31, warp = tid >> 5;
    int wm = warp >> 1, wn = warp & 1;
    int g = lane >> 2, t2 = (lane & 3) * 2;
    int m0 = blockIdx.y * 128, n0 = blockIdx.x * 128;

    uint32_t aOff = (uint32_t)((wm * 32 + (lane & 15)) * 144 + ((lane >> 4) << 3) * 2);
    uint32_t bOff = (uint32_t)((wn * 64 + ((lane >> 4) << 3) + (lane & 7)) * 144 +
                               (((lane >> 3) & 1) << 3) * 2);

    const __half* srcs[2] = { Ag + (size_t)m0 * K, Bg + (size_t)n0 * K };

    auto load_chunk = [&](int kt, int st) {
        uint32_t stb = sb + st * GST;
        #pragma unroll
        for (int b = 0; b < 2; b++) {
            const __half* base = srcs[b] + kt;
            #pragma unroll
            for (int it = 0; it < 4; it++) {
                int idx = tid + it * 256;            // 0..1023
                int r = idx >> 3, cg = idx & 7;      // 128 rows x 8 chunks(16B)
                CPA(stb + b * 18432 + r * 144 + cg * 16,
                    base + (size_t)r * K + cg * 8);
            }
        }
        CP_COMMIT();
    };

    float acc[2][8][4] = {};
    load_chunk(0, 0);
    int nch = K >> 6;
    for (int c = 0; c < nch; c++) {
        if (c + 1 < nch) { load_chunk((c + 1) * 64, (c + 1) & 1); CP_WAIT1(); }
        else             { CP_WAIT0(); }
        __syncthreads();
        uint32_t stb = sb + (c & 1) * GST;
        #pragma unroll
        for (int kk = 0; kk < 64; kk += 16) {
            uint32_t aF[2][4];
            LDSM4(aF[0], stb + aOff + kk * 2);
            LDSM4(aF[1], stb + aOff + kk * 2 + 16 * 144);
            #pragma unroll
            for (int j2 = 0; j2 < 4; j2++) {
                uint32_t bf[4];
                LDSM4(bf, stb + 18432 + bOff + j2 * 2304 + kk * 2);
                mma_f16(acc[0][2*j2],   aF[0], bf[0], bf[1]);
                mma_f16(acc[1][2*j2],   aF[1], bf[0], bf[1]);
                mma_f16(acc[0][2*j2+1], aF[0], bf[2], bf[3]);
                mma_f16(acc[1][2*j2+1], aF[1], bf[2], bf[3]);
            }
        }
        __syncthreads();
    }

    const float QSC = 0.125f * 1.44269504088896f;   // fold scale*log2(e) into q

    if (SCATTER == 1 && n0 >= 2 * Ee) {
        // ---- V^T tile: stage transposed in smem, then coalesced stores ----
        __half* sT = (__half*)smg;                   // [128 n][136 pitch] half
        #pragma unroll
        for (int i = 0; i < 2; i++) {
            #pragma unroll
            for (int e2 = 0; e2 < 2; e2++) {
                int ml = wm * 32 + i * 16 + g + e2 * 8;
                #pragma unroll
                for (int j = 0; j < 8; j++) {
                    int nl = wn * 64 + j * 8 + t2;
                    int n = n0 + nl;
                    float v0 = acc[i][j][e2*2+0] + bias[n];
                    float v1 = acc[i][j][e2*2+1] + bias[n+1];
                    sT[nl * 136 + ml]       = __float2half(v0);
                    sT[(nl + 1) * 136 + ml] = __float2half(v1);
                }
            }
        }
        __syncthreads();
        // write out: row = local n (d), contiguous along s (m)
        int b = m0 >> 11, s0 = m0 & 2047;
        int row = tid >> 1, hseg = tid & 1;          // 128 rows x 2 half-rows
        int e = (n0 & 1023) + row;
        int hh = e >> 6, d = e & 63;
        __half* dst = Vth + ((size_t)(b * Hh + hh) * Dd + d) * Sq + s0 + hseg * 64;
        const __half* src = sT + row * 136 + hseg * 64;
        #pragma unroll
        for (int k2 = 0; k2 < 8; k2++)
            *(uint4*)(dst + k2 * 8) = *(const uint4*)(src + k2 * 8);
        return;
    }

    // epilogue (C output / q / k scatter)
    #pragma unroll
    for (int i = 0; i < 2; i++) {
        #pragma unroll
        for (int e2 = 0; e2 < 2; e2++) {
            int m = m0 + wm * 32 + i * 16 + g + e2 * 8;
            #pragma unroll
            for (int j = 0; j < 8; j++) {
                int n = n0 + wn * 64 + j * 8 + t2;
                float v0 = acc[i][j][e2*2+0] + bias[n];
                float v1 = acc[i][j][e2*2+1] + bias[n+1];
                if (SCATTER == 0) {
                    *(float2*)(C + (size_t)m * N + n) = make_float2(v0, v1);
                } else {
                    int part = n >> 10, e = n & 1023, hh = e >> 6, d = e & 63;
                    int b = m >> 11, s = m & 2047;
                    int bh = b * Hh + hh;
                    if (part == 0) {
                        size_t i0 = ((size_t)bh * Sq + s) * Dd + d;
                        *(__half2*)(Qh + i0) =
                            __half2(__float2half(v0 * QSC), __float2half(v1 * QSC));
                    } else {
                        size_t i0 = ((size_t)bh * Sq + s) * Dd + d;
                        *(__half2*)(Kh + i0) =
                            __half2(__float2half(v0), __float2half(v1));
                    }
                }
            }
        }
    }
}

// ---------------------------------------------------------------------------
// Flash attention, single fp16, 128-key smem tiles (two 64-key compute passes)
// CTA: 128 q rows, 8 warps (16 q rows each). cp.async 2-stage, ex2 softmax.
// Grid is (bh, tile) with tile-major = GLOBAL heavy-first launch order (LPT).
// Diagonal passes skip provably-all-masked 16-key blocks in QK and PV (exact).
// smem: Q [128][72]; per stage K [128][72] + Vt [64][136].
// ---------------------------------------------------------------------------
#define AQ    18432
#define AKST  18432
#define AVST  17408
#define ASTG  (AKST + AVST)        // 35840
#define ASMEM (AQ + 2*ASTG)        // 90112

__global__ __launch_bounds__(256, 2)
void attn_mma(const __half* __restrict__ Qg, const __half* __restrict__ Khg,
              const __half* __restrict__ Vhg, __half* __restrict__ Oh)
{
    extern __shared__ __align__(16) char sma[];
    uint32_t sb = smem_u32(sma);
    int tid = threadIdx.x, lane = tid & 31, w = tid >> 5;
    int g = lane >> 2, t2 = (lane & 3) * 2;
    int bh = blockIdx.x;                        // fast dim = bh
    int qt = gridDim.y - 1 - (int)blockIdx.y;   // slow dim = tile, heavy first
    int q0 = qt * 128;
    int hflip = w & 1;                          // phase stagger (neutral, kept)

    uint32_t qOff = (uint32_t)((w * 16 + (lane & 15)) * 144 + ((lane >> 4) << 3) * 2);
    uint32_t kOff = (uint32_t)((((lane >> 4) << 3) + (lane & 7)) * 144 +
                               (((lane >> 3) & 1) << 3) * 2);
    uint32_t vOff = (uint32_t)((((lane >> 4) << 3) + (lane & 7)) * 272 +
                               (((lane >> 3) & 1) << 3) * 2);

    const __half* Khb = Khg + (size_t)bh * Sq * Dd;
    const __half* Vhb = Vhg + (size_t)bh * Dd * Sq;

    // Q tile -> smem
    {
        const __half* qp = Qg + ((size_t)bh * Sq + q0) * Dd;
        #pragma unroll
        for (int it = 0; it < 4; it++) {
            int idx = tid + it * 256;           // 0..1023
            int r = idx >> 3, cg = idx & 7;     // 128 rows x 8 chunks
            CPA(sb + r * 144 + cg * 16, qp + (size_t)r * Dd + cg * 8);
        }
        CP_COMMIT();
    }

    auto load_tile = [&](int t, int st) {
        uint32_t stb = sb + AQ + st * ASTG;
        int k0 = t * 128;
        // K: 128 key rows x 64 d
        #pragma unroll
        for (int it = 0; it < 4; it++) {
            int idx = tid + it * 256;
            int r = idx >> 3, cg = idx & 7;
            CPA(stb + r * 144 + cg * 16, Khb + (size_t)(k0 + r) * Dd + cg * 8);
        }
        // Vt: 64 d rows x 128 keys
        #pragma unroll
        for (int it = 0; it < 4; it++) {
            int idx = tid + it * 256;           // 0..1023
            int r = idx >> 4, cg = idx & 15;    // 64 rows x 16 chunks(16B)
            CPA(stb + AKST + r * 272 + cg * 16, Vhb + (size_t)r * Sq + k0 + cg * 8);
        }
        CP_COMMIT();
    };

    int T = qt + 1;
    load_tile(0, 0);

    float o[8][4] = {};
    float m0r = -1e30f, m1r = -1e30f, l0 = 0.f, l1 = 0.f;
    int qwmin = q0 + w * 16;

    for (int t = 0; t < T; t++) {
        if (t + 1 < T) { load_tile(t + 1, (t + 1) & 1); CP_WAIT1(); }
        else           { CP_WAIT0(); }
        __syncthreads();
        uint32_t kb = sb + AQ + (t & 1) * ASTG;

        #pragma unroll
        for (int hp = 0; hp < 2; hp++) {
            int h = hp ^ hflip;                   // odd warps: reverse half order
            int kbase = 128 * t + 64 * h;
            if (kbase <= qwmin + 15) {
                uint32_t kh = kb + h * 9216;          // 64 key rows into K buffer
                uint32_t vh = kb + AKST + h * 128;    // 64 key cols into Vt buffer
                int kmax = qwmin + 15;                // last unmasked key for this warp

                // ---- QK (skip fully-masked 16-key blocks) ----
                float s[8][4] = {};
                #pragma unroll
                for (int ks = 0; ks < 4; ks++) {
                    int kk = ks * 16;
                    uint32_t aF[4];
                    LDSM4(aF, sb + qOff + kk * 2);
                    #pragma unroll
                    for (int j2 = 0; j2 < 4; j2++) {
                        if (kbase + j2 * 16 <= kmax) {
                            uint32_t bf[4];
                            LDSM4(bf, kh + kOff + j2 * 2304 + kk * 2);
                            mma_f16(s[2*j2],   aF, bf[0], bf[1]);
                            mma_f16(s[2*j2+1], aF, bf[2], bf[3]);
                        }
                    }
                }

                // ---- causal mask ----
                if (kbase + 63 > qwmin) {
                    int qr0 = qwmin + g, qr1 = qwmin + g + 8;
                    #pragma unroll
                    for (int j = 0; j < 8; j++) {
                        int kbi = kbase + j * 8 + t2;
                        if (kbi     > qr0) s[j][0] = -1e30f;
                        if (kbi + 1 > qr0) s[j][1] = -1e30f;
                        if (kbi     > qr1) s[j][2] = -1e30f;
                        if (kbi + 1 > qr1) s[j][3] = -1e30f;
                    }
                }

                // ---- online softmax (base-2; q pre-scaled by log2e; MUFU ex2) ----
                float mx0 = -1e30f, mx1 = -1e30f;
                #pragma unroll
                for (int j = 0; j < 8; j++) {
                    mx0 = fmaxf(mx0, fmaxf(s[j][0], s[j][1]));
                    mx1 = fmaxf(mx1, fmaxf(s[j][2], s[j][3]));
                }
                #pragma unroll
                for (int off = 1; off < 4; off <<= 1) {
                    mx0 = fmaxf(mx0, __shfl_xor_sync(0xffffffffu, mx0, off, 4));
                    mx1 = fmaxf(mx1, __shfl_xor_sync(0xffffffffu, mx1, off, 4));
                }
                mx0 = fmaxf(mx0, m0r);
                mx1 = fmaxf(mx1, m1r);
                float al0 = ex2(m0r - mx0), al1 = ex2(m1r - mx1);
                m0r = mx0; m1r = mx1;
                l0 *= al0;  l1 *= al1;
                #pragma unroll
                for (int j = 0; j < 8; j++) {
                    s[j][0] = ex2(s[j][0] - mx0);
                    s[j][1] = ex2(s[j][1] - mx0);
                    s[j][2] = ex2(s[j][2] - mx1);
                    s[j][3] = ex2(s[j][3] - mx1);
                    l0 += s[j][0] + s[j][1];
                    l1 += s[j][2] + s[j][3];
                    o[j][0] *= al0; o[j][1] *= al0;
                    o[j][2] *= al1; o[j][3] *= al1;
                }

                // ---- PV (P single fp16; skip 16-key blocks with P == 0) ----
                #pragma unroll
                for (int ks = 0; ks < 4; ks++) {
                    if (kbase + ks * 16 <= kmax) {
                        int j0 = 2 * ks, j1 = 2 * ks + 1;
                        uint32_t pF[4];
                        pF[0] = pack2(__float2half(s[j0][0]), __float2half(s[j0][1]));
                        pF[1] = pack2(__float2half(s[j0][2]), __float2half(s[j0][3]));
                        pF[2] = pack2(__float2half(s[j1][0]), __float2half(s[j1][1]));
                        pF[3] = pack2(__float2half(s[j1][2]), __float2half(s[j1][3]));
                        #pragma unroll
                        for (int j2 = 0; j2 < 4; j2++) {
                            uint32_t vf[4];
                            LDSM4(vf, vh + vOff + j2 * 4352 + ks * 32);
                            mma_f16(o[2*j2],   pF, vf[0], vf[1]);
                            mma_f16(o[2*j2+1], pF, vf[2], vf[3]);
                        }
                    }
                }
            }
        }
        __syncthreads();
    }

    // ---- finalize ----
    #pragma unroll
    for (int off = 1; off < 4; off <<= 1) {
        l0 += __shfl_xor_sync(0xffffffffu, l0, off, 4);
        l1 += __shfl_xor_sync(0xffffffffu, l1, off, 4);
    }
    float inv0 = 1.f / l0, inv1 = 1.f / l1;
    int b = bh >> 4, hh = bh & 15;
    int r0 = q0 + w * 16 + g, r1 = r0 + 8;
    #pragma unroll
    for (int j = 0; j < 8; j++) {
        int d = j * 8 + t2;
        size_t i0 = ((size_t)(b * Sq + r0)) * Ee + hh * Dd + d;
        *(__half2*)(Oh + i0) =
            __half2(__float2half(o[j][0] * inv0), __float2half(o[j][1] * inv0));
        size_t i1 = ((size_t)(b * Sq + r1)) * Ee + hh * Dd + d;
        *(__half2*)(Oh + i1) =
            __half2(__float2half(o[j][2] * inv1), __float2half(o[j][3] * inv1));
    }
}

// ---------------------------------------------------------------------------
extern "C" void kernel_launch(void* const* d_in, const int* in_sizes, int n_in,
                              void* d_out, int out_size)
{
    const float* x      = (const float*)d_in[0];
    const float* W_attn = (const float*)d_in[1];
    const float* b_attn = (const float*)d_in[2];
    const float* W_proj = (const float*)d_in[3];
    const float* b_proj = (const float*)d_in[4];
    float* out = (float*)d_out;

    __half *xh, *wah, *wph, *qh, *kh, *vth, *oh;
    cudaGetSymbolAddress((void**)&xh, g_xh);
    cudaGetSymbolAddress((void**)&wah, g_wah);
    cudaGetSymbolAddress((void**)&wph, g_wph);
    cudaGetSymbolAddress((void**)&qh, g_qh);
    cudaGetSymbolAddress((void**)&kh, g_kh);
    cudaGetSymbolAddress((void**)&vth, g_vth);
    cudaGetSymbolAddress((void**)&oh, g_oh);

    cudaFuncSetAttribute(gemm_mma<0>, cudaFuncAttributeMaxDynamicSharedMemorySize, GSMEM);
    cudaFuncSetAttribute(gemm_mma<1>, cudaFuncAttributeMaxDynamicSharedMemorySize, GSMEM);
    cudaFuncSetAttribute(attn_mma,    cudaFuncAttributeMaxDynamicSharedMemorySize, ASMEM);

    // 0) fp32 -> fp16 conversions (single fused launch, 8 elems/thread)
    conv_all<<<(NX + NWA + NWP) / 2048, 256>>>(x, W_attn, W_proj, xh, wah, wph);

    // 1) QKV projection -> q (scaled by 0.125*log2e), k, V^T   (all fp16)
    gemm_mma<1><<<dim3(3*Ee/128, Mrows/128), 256, GSMEM>>>(
        xh, wah, b_attn, nullptr, qh, kh, vth, Mrows, 3*Ee, Ee);

    // 2) Causal flash attention -> merged-head fp16
    //    Grid (bh, tile): tile-major order => global heavy-first (LPT) schedule
    attn_mma<<<dim3(Bb*Hh, Sq/128), 256, ASMEM>>>(qh, kh, vth, oh);

    // 3) Output projection -> fp32 out (128x128 tiles — proven config)
    gemm_mma<0><<<dim3(Ee/128, Mrows/128), 256, GSMEM>>>(
        oh, wph, b_proj, out, nullptr, nullptr, nullptr, Mrows, Ee, Ee);
}